// round 1
// baseline (speedup 1.0000x reference)
#include <cuda_runtime.h>

#define NN 100000
#define NE 800000

// Scratch (device globals; no allocation allowed in kernel_launch)
__device__ float g_agg[(size_t)NN * 100];  // reused: width 100 (layer0), 64 (layers 1,2)
__device__ float g_h1[(size_t)NN * 64];
__device__ float g_h2[(size_t)NN * 64];
__device__ float g_deg[NN];

// ---------------------------------------------------------------------------
// In-degree via float atomics (computed once per call)
// ---------------------------------------------------------------------------
__global__ void deg_kernel(const int* __restrict__ dst) {
    int e = blockIdx.x * blockDim.x + threadIdx.x;
    if (e < NE) atomicAdd(&g_deg[dst[e]], 1.0f);
}

// ---------------------------------------------------------------------------
// Scatter-add aggregation: agg[dst] += h[src], vectorized float4 per thread.
// Thread t -> (edge = t / (D/4), chunk = t % (D/4)); adjacent threads cover
// adjacent float4 chunks of the same edge -> coalesced gathers, broadcast
// index loads. Atomics are spread over 100k * D addresses (low contention).
// ---------------------------------------------------------------------------
template <int D>
__global__ void scatter_kernel(const float* __restrict__ h,
                               const int* __restrict__ src,
                               const int* __restrict__ dst) {
    constexpr int CH = D / 4;
    int t = blockIdx.x * blockDim.x + threadIdx.x;
    if (t >= NE * CH) return;
    int e = t / CH;
    int c = t - e * CH;
    int s = src[e];
    int d = dst[e];
    float4 v = *reinterpret_cast<const float4*>(h + (size_t)s * D + c * 4);
    float* a = g_agg + (size_t)d * D + c * 4;
    atomicAdd(a + 0, v.x);
    atomicAdd(a + 1, v.y);
    atomicAdd(a + 2, v.z);
    atomicAdd(a + 3, v.w);
}

// ---------------------------------------------------------------------------
// Fused SAGE layer GEMM:
//   out[i,j] = relu?( h[i,:]@Ws[:,j] + (agg[i,:]/max(deg[i],1))@Wn[:,j] + b[j] )
// Block = (64 cols, 4 row-groups), 16 rows per block, 4 rows per thread.
// W loads are lane-consecutive (coalesced, L1-resident: W <= 51.2 KB total);
// h/agg row loads are warp-uniform broadcasts. No shared memory needed.
// ---------------------------------------------------------------------------
template <int K, int N, bool RELU>
__global__ void gemm_kernel(const float* __restrict__ h,
                            const float* __restrict__ Ws,
                            const float* __restrict__ Wn,
                            const float* __restrict__ bias,
                            float* __restrict__ out) {
    int col  = threadIdx.x;                      // 0..63
    int row0 = blockIdx.x * 16 + threadIdx.y;    // rows row0 + r*4, r=0..3

    float acc_s[4] = {0.f, 0.f, 0.f, 0.f};
    float acc_n[4] = {0.f, 0.f, 0.f, 0.f};

    #pragma unroll 4
    for (int k = 0; k < K; ++k) {
        float ws = (col < N) ? Ws[k * N + col] : 0.f;
        float wn = (col < N) ? Wn[k * N + col] : 0.f;
        #pragma unroll
        for (int r = 0; r < 4; ++r) {
            size_t row = (size_t)(row0 + r * 4);
            acc_s[r] = fmaf(h[row * K + k],     ws, acc_s[r]);
            acc_n[r] = fmaf(g_agg[row * K + k], wn, acc_n[r]);
        }
    }

    if (col < N) {
        float bv = bias[col];
        #pragma unroll
        for (int r = 0; r < 4; ++r) {
            int row = row0 + r * 4;
            float inv_deg = 1.0f / fmaxf(g_deg[row], 1.0f);
            float v = acc_s[r] + acc_n[r] * inv_deg + bv;
            if (RELU) v = fmaxf(v, 0.f);
            out[(size_t)row * N + col] = v;
        }
    }
}

// ---------------------------------------------------------------------------
// Launch: deg once; per layer {zero agg, scatter, fused gemm}.
// All stream-0 launches / async memsets -> graph-capturable, allocation-free.
// ---------------------------------------------------------------------------
extern "C" void kernel_launch(void* const* d_in, const int* in_sizes, int n_in,
                              void* d_out, int out_size) {
    const float* x    = (const float*)d_in[0];
    const int*   esrc = (const int*)d_in[1];
    const int*   edst = (const int*)d_in[2];
    const float* Ws0  = (const float*)d_in[3];
    const float* Wn0  = (const float*)d_in[4];
    const float* b0   = (const float*)d_in[5];
    const float* Ws1  = (const float*)d_in[6];
    const float* Wn1  = (const float*)d_in[7];
    const float* b1   = (const float*)d_in[8];
    const float* Ws2  = (const float*)d_in[9];
    const float* Wn2  = (const float*)d_in[10];
    const float* b2   = (const float*)d_in[11];
    float*       out  = (float*)d_out;

    void *p_agg, *p_deg, *p_h1, *p_h2;
    cudaGetSymbolAddress(&p_agg, g_agg);
    cudaGetSymbolAddress(&p_deg, g_deg);
    cudaGetSymbolAddress(&p_h1, g_h1);
    cudaGetSymbolAddress(&p_h2, g_h2);
    float* h1 = (float*)p_h1;
    float* h2 = (float*)p_h2;

    const int TB = 256;

    // degree (shared by all layers)
    cudaMemsetAsync(p_deg, 0, NN * sizeof(float));
    deg_kernel<<<(NE + TB - 1) / TB, TB>>>(edst);

    // ---- layer 0: x[100] -> h1[64], relu ----
    cudaMemsetAsync(p_agg, 0, (size_t)NN * 100 * sizeof(float));
    scatter_kernel<100><<<((size_t)NE * 25 + TB - 1) / TB, TB>>>(x, esrc, edst);
    gemm_kernel<100, 64, true><<<NN / 16, dim3(64, 4)>>>(x, Ws0, Wn0, b0, h1);

    // ---- layer 1: h1[64] -> h2[64], relu ----
    cudaMemsetAsync(p_agg, 0, (size_t)NN * 64 * sizeof(float));
    scatter_kernel<64><<<((size_t)NE * 16 + TB - 1) / TB, TB>>>(h1, esrc, edst);
    gemm_kernel<64, 64, true><<<NN / 16, dim3(64, 4)>>>(h1, Ws1, Wn1, b1, h2);

    // ---- layer 2: h2[64] -> out[47], no relu ----
    cudaMemsetAsync(p_agg, 0, (size_t)NN * 64 * sizeof(float));
    scatter_kernel<64><<<((size_t)NE * 16 + TB - 1) / TB, TB>>>(h2, esrc, edst);
    gemm_kernel<64, 47, false><<<NN / 16, dim3(64, 4)>>>(h2, Ws2, Wn2, b2, out);
}

// round 2
// speedup vs baseline: 1.8805x; 1.8805x over previous
#include <cuda_runtime.h>

#define NN 100000
#define NE 800000

// ---------------------------------------------------------------------------
// Device-global scratch (no allocation allowed)
// ---------------------------------------------------------------------------
__device__ float g_Z[(size_t)NN * 64];   // projected features h@Wn (stride 64 or 48)
__device__ float g_A[(size_t)NN * 64];   // aggregated neighbor term
__device__ float g_h1[(size_t)NN * 64];
__device__ float g_h2[(size_t)NN * 64];
__device__ int   g_count[NN];
__device__ int   g_off[NN + 1];
__device__ int   g_cursor[NN];
__device__ int   g_perm[NE];

// ---------------------------------------------------------------------------
// f32x2 packed-fp32 helpers (Blackwell; ptxas never auto-fuses these)
// ---------------------------------------------------------------------------
__device__ __forceinline__ unsigned long long pack2(float lo, float hi) {
    unsigned long long r;
    asm("mov.b64 %0, {%1, %2};" : "=l"(r) : "f"(lo), "f"(hi));
    return r;
}
__device__ __forceinline__ float2 unpack2(unsigned long long v) {
    float2 r;
    asm("mov.b64 {%0, %1}, %2;" : "=f"(r.x), "=f"(r.y) : "l"(v));
    return r;
}
__device__ __forceinline__ void fma2(unsigned long long& d,
                                     unsigned long long a, unsigned long long b) {
    asm("fma.rn.f32x2 %0, %1, %2, %0;" : "+l"(d) : "l"(a), "l"(b));
}

// ---------------------------------------------------------------------------
// CSR build: count -> scan (1 block) -> fill
// ---------------------------------------------------------------------------
__global__ void count_kernel(const int* __restrict__ dst) {
    int e = blockIdx.x * blockDim.x + threadIdx.x;
    if (e < NE) atomicAdd(&g_count[dst[e]], 1);
}

__global__ void scan_kernel() {
    __shared__ int part[1024];
    const int C = (NN + 1023) / 1024;   // 98
    int t = threadIdx.x;
    int base = t * C;
    int s = 0;
    for (int i = 0; i < C; ++i) {
        int idx = base + i;
        if (idx < NN) s += g_count[idx];
    }
    part[t] = s;
    __syncthreads();
    // Hillis-Steele inclusive scan
    for (int o = 1; o < 1024; o <<= 1) {
        int v = (t >= o) ? part[t - o] : 0;
        __syncthreads();
        part[t] += v;
        __syncthreads();
    }
    int run = (t > 0) ? part[t - 1] : 0;  // exclusive prefix
    for (int i = 0; i < C; ++i) {
        int idx = base + i;
        if (idx < NN) {
            g_off[idx] = run;
            g_cursor[idx] = run;
            run += g_count[idx];
        }
    }
    if (t == 0) g_off[NN] = part[1023];
}

__global__ void fill_kernel(const int* __restrict__ src, const int* __restrict__ dst) {
    int e = blockIdx.x * blockDim.x + threadIdx.x;
    if (e < NE) {
        int p = atomicAdd(&g_cursor[dst[e]], 1);
        g_perm[p] = src[e];
    }
}

// ---------------------------------------------------------------------------
// CSR gather aggregation: A[i,:] = sum_{j in in(i)} Z[j,:]  (no atomics)
// blockDim = (stride/4, 16): threadIdx.x = float4 chunk, threadIdx.y = node.
// ---------------------------------------------------------------------------
__global__ void gather_kernel(const float* __restrict__ Z, float* __restrict__ A,
                              int stride) {
    int node = blockIdx.x * 16 + threadIdx.y;
    if (node >= NN) return;
    int s = g_off[node], e = g_off[node + 1];
    const float* Zc = Z + threadIdx.x * 4;
    float4 acc = make_float4(0.f, 0.f, 0.f, 0.f);
    int j = s;
    for (; j + 4 <= e; j += 4) {
        int r0 = g_perm[j], r1 = g_perm[j + 1], r2 = g_perm[j + 2], r3 = g_perm[j + 3];
        float4 v0 = *reinterpret_cast<const float4*>(Zc + (size_t)r0 * stride);
        float4 v1 = *reinterpret_cast<const float4*>(Zc + (size_t)r1 * stride);
        float4 v2 = *reinterpret_cast<const float4*>(Zc + (size_t)r2 * stride);
        float4 v3 = *reinterpret_cast<const float4*>(Zc + (size_t)r3 * stride);
        acc.x += (v0.x + v1.x) + (v2.x + v3.x);
        acc.y += (v0.y + v1.y) + (v2.y + v3.y);
        acc.z += (v0.z + v1.z) + (v2.z + v3.z);
        acc.w += (v0.w + v1.w) + (v2.w + v3.w);
    }
    for (; j < e; ++j) {
        int r = g_perm[j];
        float4 v = *reinterpret_cast<const float4*>(Zc + (size_t)r * stride);
        acc.x += v.x; acc.y += v.y; acc.z += v.z; acc.w += v.w;
    }
    *reinterpret_cast<float4*>(A + (size_t)node * stride + threadIdx.x * 4) = acc;
}

// ---------------------------------------------------------------------------
// f32x2 register-tiled GEMM: out = H @ W  [+ A/deg + bias, relu]
// Block tile 128 rows x 64 cols; blockDim(16,16); per thread 8 rows x 4 cols
// held as 16 f32x2 accumulators (row-pairs in lanes).
// Smem h-tile stored transposed [k][row] so row-pairs load as one LDS.64.
// ---------------------------------------------------------------------------
template <int N>
__device__ __forceinline__ void mma_step(const float* __restrict__ W, int k, int c0,
                                         const float (*hs)[132], int kk, int r0,
                                         unsigned long long acc[4][4]) {
    unsigned long long w2[4];
    if constexpr (N % 4 == 0) {
        float4 wv = *reinterpret_cast<const float4*>(W + (size_t)k * N + c0);
        w2[0] = pack2(wv.x, wv.x);
        w2[1] = pack2(wv.y, wv.y);
        w2[2] = pack2(wv.z, wv.z);
        w2[3] = pack2(wv.w, wv.w);
    } else {
        #pragma unroll
        for (int j = 0; j < 4; ++j) {
            int c = c0 + j;
            float w = (c < N) ? W[(size_t)k * N + c] : 0.f;
            w2[j] = pack2(w, w);
        }
    }
    #pragma unroll
    for (int rp = 0; rp < 4; ++rp) {
        unsigned long long h2 =
            *reinterpret_cast<const unsigned long long*>(&hs[kk][r0 + 2 * rp]);
        #pragma unroll
        for (int j = 0; j < 4; ++j) fma2(acc[rp][j], h2, w2[j]);
    }
}

template <int K, int N, int OS, int AS, bool EPI, bool RELU>
__global__ __launch_bounds__(256) void gemm_kernel(
    const float* __restrict__ H, const float* __restrict__ W,
    const float* __restrict__ bias, const float* __restrict__ A,
    float* __restrict__ out) {
    constexpr int KK = 32;
    __shared__ float hs[KK][132];

    int tx = threadIdx.x, ty = threadIdx.y;
    int tid = ty * 16 + tx;
    int rowBase = blockIdx.x * 128;
    int c0 = tx * 4;
    int r0 = ty * 8;

    unsigned long long acc[4][4];
    #pragma unroll
    for (int rp = 0; rp < 4; ++rp)
        #pragma unroll
        for (int j = 0; j < 4; ++j) acc[rp][j] = 0ull;

    for (int k0 = 0; k0 < K; k0 += KK) {
        int kc = (K - k0 < KK) ? (K - k0) : KK;
        __syncthreads();
        if (kc == KK) {
            // 128 rows x 32 k-floats = 1024 float4 loads; coalesced over q
            #pragma unroll
            for (int i = tid; i < 128 * 8; i += 256) {
                int row = i >> 3, q = i & 7;
                int rg = rowBase + row; if (rg > NN - 1) rg = NN - 1;
                float4 v = *reinterpret_cast<const float4*>(H + (size_t)rg * K + k0 + q * 4);
                int kk = q * 4;
                hs[kk + 0][row] = v.x; hs[kk + 1][row] = v.y;
                hs[kk + 2][row] = v.z; hs[kk + 3][row] = v.w;
            }
        } else {
            for (int i = tid; i < 128 * kc; i += 256) {
                int row = i / kc, kk = i - row * kc;
                int rg = rowBase + row; if (rg > NN - 1) rg = NN - 1;
                hs[kk][row] = H[(size_t)rg * K + k0 + kk];
            }
        }
        __syncthreads();
        if (kc == KK) {
            #pragma unroll
            for (int kk = 0; kk < KK; ++kk)
                mma_step<N>(W, k0 + kk, c0, hs, kk, r0, acc);
        } else {
            for (int kk = 0; kk < kc; ++kk)
                mma_step<N>(W, k0 + kk, c0, hs, kk, r0, acc);
        }
    }

    // ---- epilogue ----
    if constexpr (N % 4 == 0) {
        float4 bv = make_float4(0.f, 0.f, 0.f, 0.f);
        if (EPI) bv = *reinterpret_cast<const float4*>(bias + c0);
        #pragma unroll
        for (int rp = 0; rp < 4; ++rp) {
            float2 u0 = unpack2(acc[rp][0]);
            float2 u1 = unpack2(acc[rp][1]);
            float2 u2 = unpack2(acc[rp][2]);
            float2 u3 = unpack2(acc[rp][3]);
            int rowe = rowBase + r0 + 2 * rp;
            #pragma unroll
            for (int lane = 0; lane < 2; ++lane) {
                int row = rowe + lane;
                if (row >= NN) continue;
                float4 o = lane ? make_float4(u0.y, u1.y, u2.y, u3.y)
                                : make_float4(u0.x, u1.x, u2.x, u3.x);
                if (EPI) {
                    int dg = g_off[row + 1] - g_off[row];
                    float inv = 1.0f / fmaxf((float)dg, 1.0f);
                    float4 av = *reinterpret_cast<const float4*>(A + (size_t)row * AS + c0);
                    o.x += av.x * inv + bv.x;
                    o.y += av.y * inv + bv.y;
                    o.z += av.z * inv + bv.z;
                    o.w += av.w * inv + bv.w;
                }
                if (RELU) {
                    o.x = fmaxf(o.x, 0.f); o.y = fmaxf(o.y, 0.f);
                    o.z = fmaxf(o.z, 0.f); o.w = fmaxf(o.w, 0.f);
                }
                *reinterpret_cast<float4*>(out + (size_t)row * OS + c0) = o;
            }
        }
    } else {
        #pragma unroll
        for (int rp = 0; rp < 4; ++rp) {
            float2 u[4] = {unpack2(acc[rp][0]), unpack2(acc[rp][1]),
                           unpack2(acc[rp][2]), unpack2(acc[rp][3])};
            int rowe = rowBase + r0 + 2 * rp;
            #pragma unroll
            for (int lane = 0; lane < 2; ++lane) {
                int row = rowe + lane;
                if (row >= NN) continue;
                float inv = 0.f;
                if (EPI) {
                    int dg = g_off[row + 1] - g_off[row];
                    inv = 1.0f / fmaxf((float)dg, 1.0f);
                }
                #pragma unroll
                for (int j = 0; j < 4; ++j) {
                    int c = c0 + j;
                    if (c >= N) continue;
                    float v = lane ? u[j].y : u[j].x;
                    if (EPI) v += A[(size_t)row * AS + c] * inv + bias[c];
                    if (RELU) v = fmaxf(v, 0.f);
                    out[(size_t)row * OS + c] = v;
                }
            }
        }
    }
}

// ---------------------------------------------------------------------------
// Launch
// ---------------------------------------------------------------------------
extern "C" void kernel_launch(void* const* d_in, const int* in_sizes, int n_in,
                              void* d_out, int out_size) {
    const float* x    = (const float*)d_in[0];
    const int*   esrc = (const int*)d_in[1];
    const int*   edst = (const int*)d_in[2];
    const float* Ws0  = (const float*)d_in[3];
    const float* Wn0  = (const float*)d_in[4];
    const float* b0   = (const float*)d_in[5];
    const float* Ws1  = (const float*)d_in[6];
    const float* Wn1  = (const float*)d_in[7];
    const float* b1   = (const float*)d_in[8];
    const float* Ws2  = (const float*)d_in[9];
    const float* Wn2  = (const float*)d_in[10];
    const float* b2   = (const float*)d_in[11];
    float*       out  = (float*)d_out;

    void *p_Z, *p_A, *p_h1, *p_h2, *p_count;
    cudaGetSymbolAddress(&p_Z, g_Z);
    cudaGetSymbolAddress(&p_A, g_A);
    cudaGetSymbolAddress(&p_h1, g_h1);
    cudaGetSymbolAddress(&p_h2, g_h2);
    cudaGetSymbolAddress(&p_count, g_count);
    float* Z  = (float*)p_Z;
    float* A  = (float*)p_A;
    float* h1 = (float*)p_h1;
    float* h2 = (float*)p_h2;

    const int TB = 256;
    const int GEMM_GRID = (NN + 127) / 128;       // 782
    const int GATHER_GRID = (NN + 15) / 16;       // 6250

    // ---- CSR build ----
    cudaMemsetAsync(p_count, 0, NN * sizeof(int));
    count_kernel<<<(NE + TB - 1) / TB, TB>>>(edst);
    scan_kernel<<<1, 1024>>>();
    fill_kernel<<<(NE + TB - 1) / TB, TB>>>(esrc, edst);

    // ---- layer 0: x[100] -> h1[64] ----
    gemm_kernel<100, 64, 64, 64, false, false><<<GEMM_GRID, dim3(16, 16)>>>(x, Wn0, nullptr, nullptr, Z);
    gather_kernel<<<GATHER_GRID, dim3(16, 16)>>>(Z, A, 64);
    gemm_kernel<100, 64, 64, 64, true, true><<<GEMM_GRID, dim3(16, 16)>>>(x, Ws0, b0, A, h1);

    // ---- layer 1: h1[64] -> h2[64] ----
    gemm_kernel<64, 64, 64, 64, false, false><<<GEMM_GRID, dim3(16, 16)>>>(h1, Wn1, nullptr, nullptr, Z);
    gather_kernel<<<GATHER_GRID, dim3(16, 16)>>>(Z, A, 64);
    gemm_kernel<64, 64, 64, 64, true, true><<<GEMM_GRID, dim3(16, 16)>>>(h1, Ws1, b1, A, h2);

    // ---- layer 2: h2[64] -> out[47] (Z padded to stride 48) ----
    gemm_kernel<64, 47, 48, 48, false, false><<<GEMM_GRID, dim3(16, 16)>>>(h2, Wn2, nullptr, nullptr, Z);
    gather_kernel<<<GATHER_GRID, dim3(12, 16)>>>(Z, A, 48);
    gemm_kernel<64, 47, 47, 48, true, false><<<GEMM_GRID, dim3(16, 16)>>>(h2, Ws2, b2, A, out);
}

// round 4
// speedup vs baseline: 2.0169x; 1.0725x over previous
#include <cuda_runtime.h>
#include <cuda_bf16.h>
#include <cstdint>

#define NN 100000
#define NE 800000

// ---------------------------------------------------------------------------
// Device-global scratch (no allocation allowed anywhere)
// ---------------------------------------------------------------------------
__device__ float g_Z[(size_t)NN * 64];    // H @ Wn   (cols 0-63 of stacked GEMM)
__device__ float g_S[(size_t)NN * 64];    // H @ Ws   (cols 64-127)
__device__ float g_H1[(size_t)NN * 64];
__device__ float g_H2[(size_t)NN * 64];
__device__ __nv_bfloat16 g_B0hi[128 * 112];
__device__ __nv_bfloat16 g_B0lo[128 * 112];
__device__ __nv_bfloat16 g_B1hi[128 * 64];
__device__ __nv_bfloat16 g_B1lo[128 * 64];
__device__ __nv_bfloat16 g_B2hi[128 * 64];
__device__ __nv_bfloat16 g_B2lo[128 * 64];
__device__ int g_count[NN];
__device__ int g_off[NN + 1];
__device__ int g_cursor[NN];
__device__ int g_perm[NE];

// ---------------------------------------------------------------------------
// CSR build: count -> scan -> fill
// ---------------------------------------------------------------------------
__global__ void count_kernel(const int* __restrict__ dst) {
    int e = blockIdx.x * blockDim.x + threadIdx.x;
    if (e < NE) atomicAdd(&g_count[dst[e]], 1);
}
__global__ void scan_kernel() {
    __shared__ int part[1024];
    const int C = (NN + 1023) / 1024;
    int t = threadIdx.x, base = t * C, s = 0;
    for (int i = 0; i < C; ++i) { int idx = base + i; if (idx < NN) s += g_count[idx]; }
    part[t] = s;
    __syncthreads();
    for (int o = 1; o < 1024; o <<= 1) {
        int v = (t >= o) ? part[t - o] : 0;
        __syncthreads();
        part[t] += v;
        __syncthreads();
    }
    int run = (t > 0) ? part[t - 1] : 0;
    for (int i = 0; i < C; ++i) {
        int idx = base + i;
        if (idx < NN) { g_off[idx] = run; g_cursor[idx] = run; run += g_count[idx]; }
    }
    if (t == 0) g_off[NN] = part[1023];
}
__global__ void fill_kernel(const int* __restrict__ src, const int* __restrict__ dst) {
    int e = blockIdx.x * blockDim.x + threadIdx.x;
    if (e < NE) {
        int p = atomicAdd(&g_cursor[dst[e]], 1);
        g_perm[p] = src[e];
    }
}

// ---------------------------------------------------------------------------
// Weight prep: B = [Wn^T ; Ws^T]  -> [128, KPAD] bf16 hi/lo, zero padded
// ---------------------------------------------------------------------------
__device__ __forceinline__ void split_bf16(float v, __nv_bfloat16& hi, __nv_bfloat16& lo) {
    hi = __float2bfloat16(v);
    lo = __float2bfloat16(v - __bfloat162float(hi));
}
__global__ void wprep_kernel(const float* __restrict__ Wn, const float* __restrict__ Ws,
                             int K, int N, int KPAD,
                             __nv_bfloat16* __restrict__ Bhi,
                             __nv_bfloat16* __restrict__ Blo) {
    int total = 128 * KPAD;
    for (int i = blockIdx.x * blockDim.x + threadIdx.x; i < total;
         i += gridDim.x * blockDim.x) {
        int n = i / KPAD, k = i - n * KPAD;
        float v = 0.f;
        if (n < 64) { if (n < N && k < K) v = Wn[k * N + n]; }
        else        { int m = n - 64; if (m < N && k < K) v = Ws[k * N + m]; }
        __nv_bfloat16 hi, lo; split_bf16(v, hi, lo);
        Bhi[i] = hi; Blo[i] = lo;
    }
}

// ---------------------------------------------------------------------------
// mma.sync bf16 GEMM with 3-term split, D[128-row tile, 128 cols] per CTA.
// blockDim 256 (8 warps), warp handles 16 rows. N=128 stacked: Z | S.
// ---------------------------------------------------------------------------
__device__ __forceinline__ void mma16816(float c[4], const uint32_t a[4],
                                         uint32_t b0, uint32_t b1) {
    asm volatile(
        "mma.sync.aligned.m16n8k16.row.col.f32.bf16.bf16.f32 "
        "{%0,%1,%2,%3}, {%4,%5,%6,%7}, {%8,%9}, {%0,%1,%2,%3};"
        : "+f"(c[0]), "+f"(c[1]), "+f"(c[2]), "+f"(c[3])
        : "r"(a[0]), "r"(a[1]), "r"(a[2]), "r"(a[3]), "r"(b0), "r"(b1));
}
__device__ __forceinline__ uint32_t pack_hi(float x, float y) {
    __nv_bfloat162 p(__float2bfloat16(x), __float2bfloat16(y));
    return *reinterpret_cast<uint32_t*>(&p);
}
__device__ __forceinline__ uint32_t pack_lo(float x, float y) {
    __nv_bfloat16 hx = __float2bfloat16(x), hy = __float2bfloat16(y);
    __nv_bfloat162 p(__float2bfloat16(x - __bfloat162float(hx)),
                     __float2bfloat16(y - __bfloat162float(hy)));
    return *reinterpret_cast<uint32_t*>(&p);
}

template <int K, int KPAD, int HS>
__global__ __launch_bounds__(256) void gemm_mma(
    const float* __restrict__ H,
    const __nv_bfloat16* __restrict__ Bhi, const __nv_bfloat16* __restrict__ Blo,
    float* __restrict__ Z, float* __restrict__ S) {
    constexpr int KSTEPS = KPAD / 16;
    int tid = threadIdx.x;
    int w = tid >> 5, lane = tid & 31;
    int g = lane >> 2, q = lane & 3;
    int r0 = blockIdx.x * 128 + w * 16;

    int rowA = r0 + g;     if (rowA >= NN) rowA = NN - 1;
    int rowB = r0 + g + 8; if (rowB >= NN) rowB = NN - 1;
    const float* HA = H + (size_t)rowA * HS;
    const float* HB = H + (size_t)rowB * HS;

    float acc[16][4];
    #pragma unroll
    for (int nt = 0; nt < 16; ++nt)
        #pragma unroll
        for (int j = 0; j < 4; ++j) acc[nt][j] = 0.f;

    #pragma unroll
    for (int ks = 0; ks < KSTEPS; ++ks) {
        int k0 = ks * 16;
        int c1 = k0 + 2 * q;       // first col pair
        int c2 = c1 + 8;           // second col pair
        float2 vA1, vB1, vA2, vB2;
        if (k0 + 16 <= K) {
            vA1 = *(const float2*)(HA + c1);
            vB1 = *(const float2*)(HB + c1);
            vA2 = *(const float2*)(HA + c2);
            vB2 = *(const float2*)(HB + c2);
        } else {  // guarded tail (layer 0 only)
            vA1.x = (c1     < K) ? HA[c1]     : 0.f;
            vA1.y = (c1 + 1 < K) ? HA[c1 + 1] : 0.f;
            vB1.x = (c1     < K) ? HB[c1]     : 0.f;
            vB1.y = (c1 + 1 < K) ? HB[c1 + 1] : 0.f;
            vA2.x = (c2     < K) ? HA[c2]     : 0.f;
            vA2.y = (c2 + 1 < K) ? HA[c2 + 1] : 0.f;
            vB2.x = (c2     < K) ? HB[c2]     : 0.f;
            vB2.y = (c2 + 1 < K) ? HB[c2 + 1] : 0.f;
        }
        uint32_t ahi[4] = {pack_hi(vA1.x, vA1.y), pack_hi(vB1.x, vB1.y),
                           pack_hi(vA2.x, vA2.y), pack_hi(vB2.x, vB2.y)};
        uint32_t alo[4] = {pack_lo(vA1.x, vA1.y), pack_lo(vB1.x, vB1.y),
                           pack_lo(vA2.x, vA2.y), pack_lo(vB2.x, vB2.y)};

        #pragma unroll
        for (int nt = 0; nt < 16; ++nt) {
            const __nv_bfloat16* bh = Bhi + (size_t)(nt * 8 + g) * KPAD + c1;
            const __nv_bfloat16* bl = Blo + (size_t)(nt * 8 + g) * KPAD + c1;
            uint32_t bh0 = __ldg((const uint32_t*)bh);
            uint32_t bh1 = __ldg((const uint32_t*)(bh + 8));
            uint32_t bl0 = __ldg((const uint32_t*)bl);
            uint32_t bl1 = __ldg((const uint32_t*)(bl + 8));
            mma16816(acc[nt], ahi, bh0, bh1);
            mma16816(acc[nt], ahi, bl0, bl1);
            mma16816(acc[nt], alo, bh0, bh1);
        }
    }

    // ---- epilogue: Z = cols 0-63, S = cols 64-127 ----
    int rr0 = r0 + g, rr1 = r0 + g + 8;
    #pragma unroll
    for (int nt = 0; nt < 16; ++nt) {
        float* dst = (nt < 8) ? Z : S;
        int col = ((nt & 7) * 8) + 2 * q;
        if (rr0 < NN) *(float2*)(dst + (size_t)rr0 * 64 + col) = make_float2(acc[nt][0], acc[nt][1]);
        if (rr1 < NN) *(float2*)(dst + (size_t)rr1 * 64 + col) = make_float2(acc[nt][2], acc[nt][3]);
    }
}

// ---------------------------------------------------------------------------
// Gather + epilogue: relu(S + (sum Z[perm]) / deg + bias)
// ---------------------------------------------------------------------------
__device__ __forceinline__ float4 gather_node(const float* __restrict__ Z,
                                              int node, int tx) {
    int s = g_off[node], e = g_off[node + 1];
    const float* Zc = Z + tx * 4;
    float4 acc = make_float4(0.f, 0.f, 0.f, 0.f);
    int j = s;
    for (; j + 4 <= e; j += 4) {
        int r0 = g_perm[j], r1 = g_perm[j + 1], r2 = g_perm[j + 2], r3 = g_perm[j + 3];
        float4 v0 = *(const float4*)(Zc + (size_t)r0 * 64);
        float4 v1 = *(const float4*)(Zc + (size_t)r1 * 64);
        float4 v2 = *(const float4*)(Zc + (size_t)r2 * 64);
        float4 v3 = *(const float4*)(Zc + (size_t)r3 * 64);
        acc.x += (v0.x + v1.x) + (v2.x + v3.x);
        acc.y += (v0.y + v1.y) + (v2.y + v3.y);
        acc.z += (v0.z + v1.z) + (v2.z + v3.z);
        acc.w += (v0.w + v1.w) + (v2.w + v3.w);
    }
    for (; j < e; ++j) {
        int r = g_perm[j];
        float4 v = *(const float4*)(Zc + (size_t)r * 64);
        acc.x += v.x; acc.y += v.y; acc.z += v.z; acc.w += v.w;
    }
    return acc;
}

__global__ void gather_epi_mid(const float* __restrict__ Z, const float* __restrict__ S,
                               const float* __restrict__ bias, float* __restrict__ Hout) {
    int node = blockIdx.x * 16 + threadIdx.y;
    if (node >= NN) return;
    int tx = threadIdx.x;  // 0..15
    float4 acc = gather_node(Z, node, tx);
    float inv = 1.0f / fmaxf((float)(g_off[node + 1] - g_off[node]), 1.0f);
    float4 sv = *(const float4*)(S + (size_t)node * 64 + tx * 4);
    float4 bv = *(const float4*)(bias + tx * 4);
    float4 o = make_float4(fmaxf(sv.x + acc.x * inv + bv.x, 0.f),
                           fmaxf(sv.y + acc.y * inv + bv.y, 0.f),
                           fmaxf(sv.z + acc.z * inv + bv.z, 0.f),
                           fmaxf(sv.w + acc.w * inv + bv.w, 0.f));
    *(float4*)(Hout + (size_t)node * 64 + tx * 4) = o;
}

__global__ void gather_epi_out(const float* __restrict__ Z, const float* __restrict__ S,
                               const float* __restrict__ bias, float* __restrict__ out) {
    int node = blockIdx.x * 16 + threadIdx.y;
    if (node >= NN) return;
    int tx = threadIdx.x;  // 0..11 -> cols 0..47
    float4 acc = gather_node(Z, node, tx);
    float inv = 1.0f / fmaxf((float)(g_off[node + 1] - g_off[node]), 1.0f);
    float4 sv = *(const float4*)(S + (size_t)node * 64 + tx * 4);
    float a[4] = {acc.x, acc.y, acc.z, acc.w};
    float s[4] = {sv.x, sv.y, sv.z, sv.w};
    #pragma unroll
    for (int j = 0; j < 4; ++j) {
        int c = tx * 4 + j;
        if (c < 47) out[(size_t)node * 47 + c] = s[j] + a[j] * inv + bias[c];
    }
}

// ---------------------------------------------------------------------------
// Launch
// ---------------------------------------------------------------------------
extern "C" void kernel_launch(void* const* d_in, const int* in_sizes, int n_in,
                              void* d_out, int out_size) {
    const float* x    = (const float*)d_in[0];
    const int*   esrc = (const int*)d_in[1];
    const int*   edst = (const int*)d_in[2];
    const float* Ws0  = (const float*)d_in[3];
    const float* Wn0  = (const float*)d_in[4];
    const float* b0   = (const float*)d_in[5];
    const float* Ws1  = (const float*)d_in[6];
    const float* Wn1  = (const float*)d_in[7];
    const float* b1   = (const float*)d_in[8];
    const float* Ws2  = (const float*)d_in[9];
    const float* Wn2  = (const float*)d_in[10];
    const float* b2   = (const float*)d_in[11];
    float*       out  = (float*)d_out;

    void *p_count, *p_Z, *p_S, *p_H1, *p_H2;
    void *p_B0hi, *p_B0lo, *p_B1hi, *p_B1lo, *p_B2hi, *p_B2lo;
    cudaGetSymbolAddress(&p_count, g_count);
    cudaGetSymbolAddress(&p_Z, g_Z);
    cudaGetSymbolAddress(&p_S, g_S);
    cudaGetSymbolAddress(&p_H1, g_H1);
    cudaGetSymbolAddress(&p_H2, g_H2);
    cudaGetSymbolAddress(&p_B0hi, g_B0hi); cudaGetSymbolAddress(&p_B0lo, g_B0lo);
    cudaGetSymbolAddress(&p_B1hi, g_B1hi); cudaGetSymbolAddress(&p_B1lo, g_B1lo);
    cudaGetSymbolAddress(&p_B2hi, g_B2hi); cudaGetSymbolAddress(&p_B2lo, g_B2lo);
    float* Z  = (float*)p_Z;  float* S  = (float*)p_S;
    float* H1 = (float*)p_H1; float* H2 = (float*)p_H2;

    const int TB = 256;
    const int EG = (NE + TB - 1) / TB;
    const int GG = (NN + 127) / 128;   // 782 gemm CTAs
    const int NG = (NN + 15) / 16;     // 6250 gather blocks

    // CSR build
    cudaMemsetAsync(p_count, 0, NN * sizeof(int));
    count_kernel<<<EG, TB>>>(edst);
    scan_kernel<<<1, 1024>>>();
    fill_kernel<<<EG, TB>>>(esrc, edst);

    // Weight prep (stacked + split)
    wprep_kernel<<<64, 256>>>(Wn0, Ws0, 100, 64, 112, (__nv_bfloat16*)p_B0hi, (__nv_bfloat16*)p_B0lo);
    wprep_kernel<<<64, 256>>>(Wn1, Ws1, 64, 64, 64,  (__nv_bfloat16*)p_B1hi, (__nv_bfloat16*)p_B1lo);
    wprep_kernel<<<64, 256>>>(Wn2, Ws2, 64, 47, 64,  (__nv_bfloat16*)p_B2hi, (__nv_bfloat16*)p_B2lo);

    // layer 0: x[100] -> H1[64]
    gemm_mma<100, 112, 100><<<GG, 256>>>(x, (__nv_bfloat16*)p_B0hi, (__nv_bfloat16*)p_B0lo, Z, S);
    gather_epi_mid<<<NG, dim3(16, 16)>>>(Z, S, b0, H1);

    // layer 1: H1 -> H2
    gemm_mma<64, 64, 64><<<GG, 256>>>(H1, (__nv_bfloat16*)p_B1hi, (__nv_bfloat16*)p_B1lo, Z, S);
    gather_epi_mid<<<NG, dim3(16, 16)>>>(Z, S, b1, H2);

    // layer 2: H2 -> out[47]
    gemm_mma<64, 64, 64><<<GG, 256>>>(H2, (__nv_bfloat16*)p_B2hi, (__nv_bfloat16*)p_B2lo, Z, S);
    gather_epi_out<<<NG, dim3(12, 16)>>>(Z, S, b2, out);
}

// round 6
// speedup vs baseline: 2.4974x; 1.2383x over previous
#include <cuda_runtime.h>
#include <cuda_bf16.h>
#include <cstdint>

#define NN 100000
#define NE 800000

// ---------------------------------------------------------------------------
// Device-global scratch
// ---------------------------------------------------------------------------
__device__ float g_Z[(size_t)NN * 64];
__device__ float g_S[(size_t)NN * 64];
__device__ float g_H1[(size_t)NN * 64];
__device__ float g_H2[(size_t)NN * 64];
// Packed B fragments: [kstep][nt(16)][g(8)][q(4)] -> uint4 {bh0,bh1,bl0,bl1}
__device__ uint4 g_Bp0[7 * 16 * 8 * 4];
__device__ uint4 g_Bp1[4 * 16 * 8 * 4];
__device__ uint4 g_Bp2[4 * 16 * 8 * 4];
__device__ int g_count[NN];
__device__ int g_off[NN + 1];
__device__ int g_cursor[NN];
__device__ int g_perm[NE];

// ---------------------------------------------------------------------------
// CSR build
// ---------------------------------------------------------------------------
__global__ void count_kernel(const int* __restrict__ dst) {
    int e = blockIdx.x * blockDim.x + threadIdx.x;
    if (e < NE) atomicAdd(&g_count[dst[e]], 1);
}
__global__ void scan_kernel() {
    __shared__ int part[1024];
    const int C = (NN + 1023) / 1024;
    int t = threadIdx.x, base = t * C, s = 0;
    for (int i = 0; i < C; ++i) { int idx = base + i; if (idx < NN) s += g_count[idx]; }
    part[t] = s;
    __syncthreads();
    for (int o = 1; o < 1024; o <<= 1) {
        int v = (t >= o) ? part[t - o] : 0;
        __syncthreads();
        part[t] += v;
        __syncthreads();
    }
    int run = (t > 0) ? part[t - 1] : 0;
    for (int i = 0; i < C; ++i) {
        int idx = base + i;
        if (idx < NN) { g_off[idx] = run; g_cursor[idx] = run; run += g_count[idx]; }
    }
    if (t == 0) g_off[NN] = part[1023];
}
__global__ void fill_kernel(const int* __restrict__ src, const int* __restrict__ dst) {
    int e = blockIdx.x * blockDim.x + threadIdx.x;
    if (e < NE) {
        int p = atomicAdd(&g_cursor[dst[e]], 1);
        g_perm[p] = src[e];
    }
}

// ---------------------------------------------------------------------------
// Weight prep: pack stacked B = [Wn^T ; Ws^T] into mma fragment order.
// One merged launch for all 3 layers. Thread -> (ks, nt, g, q).
// ---------------------------------------------------------------------------
__device__ __forceinline__ uint32_t bf2_hi(float x, float y) {
    __nv_bfloat162 p(__float2bfloat16(x), __float2bfloat16(y));
    return *reinterpret_cast<uint32_t*>(&p);
}
__device__ __forceinline__ uint32_t bf2_lo(float x, float y) {
    __nv_bfloat16 hx = __float2bfloat16(x), hy = __float2bfloat16(y);
    __nv_bfloat162 p(__float2bfloat16(x - __bfloat162float(hx)),
                     __float2bfloat16(y - __bfloat162float(hy)));
    return *reinterpret_cast<uint32_t*>(&p);
}
__device__ __forceinline__ float wval(const float* Wn, const float* Ws,
                                      int K, int Nout, int n, int k) {
    if (n < 64) return (n < Nout && k < K) ? Wn[k * Nout + n] : 0.f;
    int m = n - 64;
    return (m < Nout && k < K) ? Ws[k * Nout + m] : 0.f;
}
__global__ void wprep_packed(const float* __restrict__ Wn0, const float* __restrict__ Ws0,
                             const float* __restrict__ Wn1, const float* __restrict__ Ws1,
                             const float* __restrict__ Wn2, const float* __restrict__ Ws2) {
    int b = blockIdx.x, tid = threadIdx.x;
    const float *Wn, *Ws;
    uint4* Bp;
    int K, Nout, total, idx;
    if (b < 14)      { Wn = Wn0; Ws = Ws0; Bp = g_Bp0; K = 100; Nout = 64; total = 7 * 512; idx = b * 256 + tid; }
    else if (b < 22) { Wn = Wn1; Ws = Ws1; Bp = g_Bp1; K = 64;  Nout = 64; total = 4 * 512; idx = (b - 14) * 256 + tid; }
    else             { Wn = Wn2; Ws = Ws2; Bp = g_Bp2; K = 64;  Nout = 47; total = 4 * 512; idx = (b - 22) * 256 + tid; }
    if (idx >= total) return;
    int q  = idx & 3;
    int g  = (idx >> 2) & 7;
    int nt = (idx >> 5) & 15;
    int ks = idx >> 9;
    int n  = nt * 8 + g;
    int k1 = ks * 16 + 2 * q;
    int k2 = k1 + 8;
    float v0 = wval(Wn, Ws, K, Nout, n, k1);
    float v1 = wval(Wn, Ws, K, Nout, n, k1 + 1);
    float v2 = wval(Wn, Ws, K, Nout, n, k2);
    float v3 = wval(Wn, Ws, K, Nout, n, k2 + 1);
    uint4 o;
    o.x = bf2_hi(v0, v1);
    o.y = bf2_hi(v2, v3);
    o.z = bf2_lo(v0, v1);
    o.w = bf2_lo(v2, v3);
    Bp[idx] = o;
}

// ---------------------------------------------------------------------------
// GEMM: D[128 rows, 128 cols] per CTA. A staged in smem (bf16 hi/lo, padded
// rows, ldmatrix.x4 fragments). B from packed global fragments (1 LDG.128/nt).
// 3-term split: Ahi*Bhi + Ahi*Blo + Alo*Bhi, fp32 accum.
// ---------------------------------------------------------------------------
__device__ __forceinline__ void mma16816(float c[4], const uint32_t a[4],
                                         uint32_t b0, uint32_t b1) {
    asm volatile(
        "mma.sync.aligned.m16n8k16.row.col.f32.bf16.bf16.f32 "
        "{%0,%1,%2,%3}, {%4,%5,%6,%7}, {%8,%9}, {%0,%1,%2,%3};"
        : "+f"(c[0]), "+f"(c[1]), "+f"(c[2]), "+f"(c[3])
        : "r"(a[0]), "r"(a[1]), "r"(a[2]), "r"(a[3]), "r"(b0), "r"(b1));
}
__device__ __forceinline__ void ldsm_x4(uint32_t r[4], uint32_t addr) {
    asm volatile("ldmatrix.sync.aligned.m8n8.x4.shared.b16 {%0,%1,%2,%3}, [%4];"
                 : "=r"(r[0]), "=r"(r[1]), "=r"(r[2]), "=r"(r[3]) : "r"(addr));
}
__device__ __forceinline__ uint32_t smem_u32(const void* p) {
    uint32_t a;
    asm("{ .reg .u64 t; cvta.to.shared.u64 t, %1; cvt.u32.u64 %0, t; }" : "=r"(a) : "l"(p));
    return a;
}

template <int K, int KPAD, int HS>
__global__ __launch_bounds__(256) void gemm_mma(
    const float* __restrict__ H, const uint4* __restrict__ Bp,
    float* __restrict__ Z, float* __restrict__ S) {
    constexpr int KSTEPS = KPAD / 16;
    constexpr int KPADS = KPAD + 8;          // +16B row pad: conflict-free ldmatrix
    extern __shared__ __nv_bfloat16 sm[];
    __nv_bfloat16* shi = sm;                  // [128][KPADS]
    __nv_bfloat16* slo = sm + 128 * KPADS;

    int tid = threadIdx.x;
    int w = tid >> 5, lane = tid & 31;
    int g = lane >> 2, q = lane & 3;
    int t = lane >> 3, r = lane & 7;
    int rowBase = blockIdx.x * 128;

    // ---- stage H -> bf16 hi/lo smem ----
    constexpr int C4 = KPAD / 4;
    for (int i = tid; i < 128 * C4; i += 256) {
        int row = i / C4, col = (i - row * C4) * 4;
        int rg = rowBase + row; if (rg >= NN) rg = NN - 1;
        float4 v;
        if (col + 4 <= K) v = *(const float4*)(H + (size_t)rg * HS + col);
        else v = make_float4(0.f, 0.f, 0.f, 0.f);   // zero pad (K=100 tail)
        __nv_bfloat16 h0 = __float2bfloat16(v.x), h1 = __float2bfloat16(v.y);
        __nv_bfloat16 h2 = __float2bfloat16(v.z), h3 = __float2bfloat16(v.w);
        __nv_bfloat162 hp0(h0, h1), hp1(h2, h3);
        __nv_bfloat162 lp0(__float2bfloat16(v.x - __bfloat162float(h0)),
                           __float2bfloat16(v.y - __bfloat162float(h1)));
        __nv_bfloat162 lp1(__float2bfloat16(v.z - __bfloat162float(h2)),
                           __float2bfloat16(v.w - __bfloat162float(h3)));
        uint2 hw = {*(uint32_t*)&hp0, *(uint32_t*)&hp1};
        uint2 lw = {*(uint32_t*)&lp0, *(uint32_t*)&lp1};
        *(uint2*)(shi + row * KPADS + col) = hw;
        *(uint2*)(slo + row * KPADS + col) = lw;
    }
    __syncthreads();

    // ldmatrix lane address: tile t, row r
    int arow = w * 16 + (t & 1) * 8 + r;
    int acol0 = (t >> 1) * 8;
    uint32_t hi_addr = smem_u32(shi + arow * KPADS + acol0);
    uint32_t lo_addr = smem_u32(slo + arow * KPADS + acol0);

    float acc[16][4];
    #pragma unroll
    for (int nt = 0; nt < 16; ++nt)
        #pragma unroll
        for (int j = 0; j < 4; ++j) acc[nt][j] = 0.f;

    #pragma unroll
    for (int ks = 0; ks < KSTEPS; ++ks) {
        uint32_t ahi[4], alo[4];
        ldsm_x4(ahi, hi_addr + ks * 32);
        ldsm_x4(alo, lo_addr + ks * 32);
        const uint4* bp = Bp + ((size_t)ks * 16 * 32) + g * 4 + q;
        #pragma unroll
        for (int nt = 0; nt < 16; ++nt) {
            uint4 b = __ldg(bp + nt * 32);
            mma16816(acc[nt], ahi, b.x, b.y);
            mma16816(acc[nt], ahi, b.z, b.w);
            mma16816(acc[nt], alo, b.x, b.y);
        }
    }

    // ---- epilogue: cols 0-63 -> Z, 64-127 -> S ----
    int rr0 = rowBase + w * 16 + g;
    int rr1 = rr0 + 8;
    #pragma unroll
    for (int nt = 0; nt < 16; ++nt) {
        float* dst = (nt < 8) ? Z : S;
        int col = ((nt & 7) * 8) + 2 * q;
        if (rr0 < NN) *(float2*)(dst + (size_t)rr0 * 64 + col) = make_float2(acc[nt][0], acc[nt][1]);
        if (rr1 < NN) *(float2*)(dst + (size_t)rr1 * 64 + col) = make_float2(acc[nt][2], acc[nt][3]);
    }
}

// ---------------------------------------------------------------------------
// Gather + epilogue: relu(S + (sum Z[perm]) / deg + bias)
// ---------------------------------------------------------------------------
__device__ __forceinline__ float4 gather_node(const float* __restrict__ Z,
                                              int node, int tx) {
    int s = g_off[node], e = g_off[node + 1];
    const float* Zc = Z + tx * 4;
    float4 a0 = make_float4(0.f, 0.f, 0.f, 0.f);
    float4 a1 = make_float4(0.f, 0.f, 0.f, 0.f);
    int j = s;
    for (; j + 8 <= e; j += 8) {
        int r0 = g_perm[j],     r1 = g_perm[j + 1], r2 = g_perm[j + 2], r3 = g_perm[j + 3];
        int r4 = g_perm[j + 4], r5 = g_perm[j + 5], r6 = g_perm[j + 6], r7 = g_perm[j + 7];
        float4 v0 = *(const float4*)(Zc + (size_t)r0 * 64);
        float4 v1 = *(const float4*)(Zc + (size_t)r1 * 64);
        float4 v2 = *(const float4*)(Zc + (size_t)r2 * 64);
        float4 v3 = *(const float4*)(Zc + (size_t)r3 * 64);
        float4 v4 = *(const float4*)(Zc + (size_t)r4 * 64);
        float4 v5 = *(const float4*)(Zc + (size_t)r5 * 64);
        float4 v6 = *(const float4*)(Zc + (size_t)r6 * 64);
        float4 v7 = *(const float4*)(Zc + (size_t)r7 * 64);
        a0.x += (v0.x + v1.x) + (v2.x + v3.x);
        a0.y += (v0.y + v1.y) + (v2.y + v3.y);
        a0.z += (v0.z + v1.z) + (v2.z + v3.z);
        a0.w += (v0.w + v1.w) + (v2.w + v3.w);
        a1.x += (v4.x + v5.x) + (v6.x + v7.x);
        a1.y += (v4.y + v5.y) + (v6.y + v7.y);
        a1.z += (v4.z + v5.z) + (v6.z + v7.z);
        a1.w += (v4.w + v5.w) + (v6.w + v7.w);
    }
    for (; j < e; ++j) {
        int rr = g_perm[j];
        float4 v = *(const float4*)(Zc + (size_t)rr * 64);
        a0.x += v.x; a0.y += v.y; a0.z += v.z; a0.w += v.w;
    }
    return make_float4(a0.x + a1.x, a0.y + a1.y, a0.z + a1.z, a0.w + a1.w);
}

__global__ void gather_epi_mid(const float* __restrict__ Z, const float* __restrict__ S,
                               const float* __restrict__ bias, float* __restrict__ Hout) {
    int node = blockIdx.x * 16 + threadIdx.y;
    if (node >= NN) return;
    int tx = threadIdx.x;
    float4 acc = gather_node(Z, node, tx);
    float inv = 1.0f / fmaxf((float)(g_off[node + 1] - g_off[node]), 1.0f);
    float4 sv = *(const float4*)(S + (size_t)node * 64 + tx * 4);
    float4 bv = *(const float4*)(bias + tx * 4);
    float4 o = make_float4(fmaxf(sv.x + acc.x * inv + bv.x, 0.f),
                           fmaxf(sv.y + acc.y * inv + bv.y, 0.f),
                           fmaxf(sv.z + acc.z * inv + bv.z, 0.f),
                           fmaxf(sv.w + acc.w * inv + bv.w, 0.f));
    *(float4*)(Hout + (size_t)node * 64 + tx * 4) = o;
}

__global__ void gather_epi_out(const float* __restrict__ Z, const float* __restrict__ S,
                               const float* __restrict__ bias, float* __restrict__ out) {
    int node = blockIdx.x * 16 + threadIdx.y;
    if (node >= NN) return;
    int tx = threadIdx.x;  // 0..11 -> cols 0..47
    float4 acc = gather_node(Z, node, tx);
    float inv = 1.0f / fmaxf((float)(g_off[node + 1] - g_off[node]), 1.0f);
    float4 sv = *(const float4*)(S + (size_t)node * 64 + tx * 4);
    float a[4] = {acc.x, acc.y, acc.z, acc.w};
    float s[4] = {sv.x, sv.y, sv.z, sv.w};
    #pragma unroll
    for (int j = 0; j < 4; ++j) {
        int c = tx * 4 + j;
        if (c < 47) out[(size_t)node * 47 + c] = s[j] + a[j] * inv + bias[c];
    }
}

// ---------------------------------------------------------------------------
// Launch
// ---------------------------------------------------------------------------
extern "C" void kernel_launch(void* const* d_in, const int* in_sizes, int n_in,
                              void* d_out, int out_size) {
    const float* x    = (const float*)d_in[0];
    const int*   esrc = (const int*)d_in[1];
    const int*   edst = (const int*)d_in[2];
    const float* Ws0  = (const float*)d_in[3];
    const float* Wn0  = (const float*)d_in[4];
    const float* b0   = (const float*)d_in[5];
    const float* Ws1  = (const float*)d_in[6];
    const float* Wn1  = (const float*)d_in[7];
    const float* b1   = (const float*)d_in[8];
    const float* Ws2  = (const float*)d_in[9];
    const float* Wn2  = (const float*)d_in[10];
    const float* b2   = (const float*)d_in[11];
    float*       out  = (float*)d_out;

    void *p_count, *p_Z, *p_S, *p_H1, *p_H2, *p_Bp0, *p_Bp1, *p_Bp2;
    cudaGetSymbolAddress(&p_count, g_count);
    cudaGetSymbolAddress(&p_Z, g_Z);
    cudaGetSymbolAddress(&p_S, g_S);
    cudaGetSymbolAddress(&p_H1, g_H1);
    cudaGetSymbolAddress(&p_H2, g_H2);
    cudaGetSymbolAddress(&p_Bp0, g_Bp0);
    cudaGetSymbolAddress(&p_Bp1, g_Bp1);
    cudaGetSymbolAddress(&p_Bp2, g_Bp2);
    float* Z  = (float*)p_Z;  float* S  = (float*)p_S;
    float* H1 = (float*)p_H1; float* H2 = (float*)p_H2;

    // dynamic smem: layer0 = 2*128*120*2 = 61440 B; layers 1/2 = 2*128*72*2 = 36864 B
    cudaFuncSetAttribute(gemm_mma<100, 112, 100>, cudaFuncAttributeMaxDynamicSharedMemorySize, 61440);
    cudaFuncSetAttribute(gemm_mma<64, 64, 64>,    cudaFuncAttributeMaxDynamicSharedMemorySize, 36864);

    const int TB = 256;
    const int EG = (NE + TB - 1) / TB;
    const int GG = (NN + 127) / 128;   // 782
    const int NG = (NN + 15) / 16;     // 6250

    // CSR build
    cudaMemsetAsync(p_count, 0, NN * sizeof(int));
    count_kernel<<<EG, TB>>>(edst);
    scan_kernel<<<1, 1024>>>();
    fill_kernel<<<EG, TB>>>(esrc, edst);

    // merged packed weight prep (30 blocks: 14 + 8 + 8)
    wprep_packed<<<30, 256>>>(Wn0, Ws0, Wn1, Ws1, Wn2, Ws2);

    // layer 0
    gemm_mma<100, 112, 100><<<GG, 256, 61440>>>(x, (const uint4*)p_Bp0, Z, S);
    gather_epi_mid<<<NG, dim3(16, 16)>>>(Z, S, b0, H1);

    // layer 1
    gemm_mma<64, 64, 64><<<GG, 256, 36864>>>(H1, (const uint4*)p_Bp1, Z, S);
    gather_epi_mid<<<NG, dim3(16, 16)>>>(Z, S, b1, H2);

    // layer 2
    gemm_mma<64, 64, 64><<<GG, 256, 36864>>>(H2, (const uint4*)p_Bp2, Z, S);
    gather_epi_out<<<NG, dim3(12, 16)>>>(Z, S, b2, out);
}